// round 8
// baseline (speedup 1.0000x reference)
#include <cuda_runtime.h>
#include <cuda_fp16.h>
#include <cstdint>

// ---------------- problem constants ----------------
#define Bc   2
#define Tc   4096
#define Ec   512
#define Hc   8
#define Dc   64
#define FFc  2048
#define Lc   2
#define WINc 16
#define NW   33
#define ROWS (Bc*Tc)      // 8192
#define EPSc 1e-5f
#define QKVN (3*Ec)       // 1536

#define WT_QKV_OFF 0
#define WT_WO_OFF  (3*Ec*Ec)
#define WT_W1_OFF  (4*Ec*Ec)
#define WT_W2_OFF  (WT_W1_OFF + FFc*Ec)
#define WT_LAYER   (WT_W2_OFF + Ec*FFc)

// ---------------- scratch ----------------
__device__ __half g_h   [(size_t)ROWS*Ec];
__device__ __half g_qkv [(size_t)ROWS*QKVN];
__device__ __half g_ao  [(size_t)ROWS*Ec];
__device__ __half g_ff  [(size_t)ROWS*FFc];
__device__ __half g_wt  [(size_t)Lc*WT_LAYER];

// ---------------- helpers ----------------
__device__ __forceinline__ uint32_t smem_u32(const void* p) {
    uint32_t a;
    asm("{ .reg .u64 t; cvta.to.shared.u64 t, %1; cvt.u32.u64 %0, t; }" : "=r"(a) : "l"(p));
    return a;
}
#define SW128(x) ((x) ^ (((x) >> 3) & 0x70))

#define CP16(dst, src) \
    asm volatile("cp.async.cg.shared.global [%0], [%1], 16;" :: "r"(dst), "l"(src) : "memory")
#define CPCOMMIT() asm volatile("cp.async.commit_group;" ::: "memory")

__device__ __forceinline__ void ldmx4(uint32_t& r0, uint32_t& r1, uint32_t& r2, uint32_t& r3,
                                      uint32_t addr) {
    asm volatile("ldmatrix.sync.aligned.m8n8.x4.shared.b16 {%0,%1,%2,%3}, [%4];"
                 : "=r"(r0), "=r"(r1), "=r"(r2), "=r"(r3) : "r"(addr));
}
__device__ __forceinline__ void mma16816(float* c, const uint32_t* a, const uint32_t* b) {
    asm volatile("mma.sync.aligned.m16n8k16.row.col.f32.f16.f16.f32 "
                 "{%0,%1,%2,%3}, {%4,%5,%6,%7}, {%8,%9}, {%0,%1,%2,%3};"
                 : "+f"(c[0]), "+f"(c[1]), "+f"(c[2]), "+f"(c[3])
                 : "r"(a[0]), "r"(a[1]), "r"(a[2]), "r"(a[3]), "r"(b[0]), "r"(b[1]));
}

// ---------------- embedding ----------------
__global__ void embed_kernel(const int* __restrict__ tokens,
                             const float* __restrict__ tok_emb,
                             const float* __restrict__ pos_emb,
                             float* __restrict__ x) {
    int row = blockIdx.x;
    int t   = row & (Tc - 1);
    int tok = tokens[row];
    int e   = threadIdx.x * 4;
    float4 a = *(const float4*)(tok_emb + (size_t)tok * Ec + e);
    float4 p = *(const float4*)(pos_emb + (size_t)t   * Ec + e);
    a.x += p.x; a.y += p.y; a.z += p.z; a.w += p.w;
    *(float4*)(x + (size_t)row * Ec + e) = a;
}

// ---------------- layernorm -> fp16 ----------------
__global__ void ln_kernel(const float* __restrict__ x,
                          const float* __restrict__ g,
                          const float* __restrict__ b,
                          __half* __restrict__ y) {
    int warp = (blockIdx.x * blockDim.x + threadIdx.x) >> 5;
    int lane = threadIdx.x & 31;
    if (warp >= ROWS) return;
    const float* xr = x + (size_t)warp * Ec;
    float v[16];
    float s = 0.f;
#pragma unroll
    for (int i = 0; i < 16; i++) { v[i] = xr[lane + i * 32]; s += v[i]; }
#pragma unroll
    for (int o = 16; o > 0; o >>= 1) s += __shfl_xor_sync(0xffffffffu, s, o);
    float mean = s * (1.f / Ec);
    float ss = 0.f;
#pragma unroll
    for (int i = 0; i < 16; i++) { float d = v[i] - mean; ss += d * d; }
#pragma unroll
    for (int o = 16; o > 0; o >>= 1) ss += __shfl_xor_sync(0xffffffffu, ss, o);
    float inv = rsqrtf(ss * (1.f / Ec) + EPSc);
    size_t rb = (size_t)warp * Ec;
#pragma unroll
    for (int i = 0; i < 16; i++) {
        int idx = lane + i * 32;
        y[rb + idx] = __float2half_rn((v[i] - mean) * inv * g[idx] + b[idx]);
    }
}

// ---------------- fused weight prep (fp16 transpose, single precision) -------
__global__ void prep_kernel(const float* __restrict__ Wq, const float* __restrict__ Wk,
                            const float* __restrict__ Wv, const float* __restrict__ Wo,
                            const float* __restrict__ W1, const float* __restrict__ W2,
                            __half* __restrict__ thi) {
    int l = blockIdx.z, y = blockIdx.y;
    int K = (y == 5) ? FFc : Ec;
    int N = (y == 4) ? FFc : Ec;
    int ntiles = N >> 5;
    int nt = blockIdx.x % ntiles;
    int kt = blockIdx.x / ntiles;
    if (kt >= (K >> 5)) return;

    const float* W; size_t doff;
    switch (y) {
        case 0: W = Wq + (size_t)l * Ec * Ec;  doff = WT_QKV_OFF;            break;
        case 1: W = Wk + (size_t)l * Ec * Ec;  doff = WT_QKV_OFF + Ec * Ec;  break;
        case 2: W = Wv + (size_t)l * Ec * Ec;  doff = WT_QKV_OFF + 2*Ec*Ec;  break;
        case 3: W = Wo + (size_t)l * Ec * Ec;  doff = WT_WO_OFF;             break;
        case 4: W = W1 + (size_t)l * Ec * FFc; doff = WT_W1_OFF;             break;
        default:W = W2 + (size_t)l * FFc * Ec; doff = WT_W2_OFF;             break;
    }
    doff += (size_t)l * WT_LAYER;

    __shared__ float tile[32][33];
    int n0 = nt * 32, k0 = kt * 32;
    int tx = threadIdx.x, ty = threadIdx.y;
#pragma unroll
    for (int i = 0; i < 32; i += 8)
        tile[ty + i][tx] = W[(size_t)(k0 + ty + i) * N + n0 + tx];
    __syncthreads();
#pragma unroll
    for (int i = 0; i < 32; i += 8) {
        float v = tile[tx][ty + i];
        thi[doff + (size_t)(n0 + ty + i) * K + k0 + tx] = __float2half_rn(v);
    }
}

// ---------------- mma.sync GEMM: CTA 128x256, warp 64x64, single fp16 pass ---
// EPI: 0 = fp16 out; 1 = bias+relu -> fp16; 2 = bias+residual fp32
#define GBM 128
#define GBN 256
#define GBK 64
#define A_OFF   0
#define B_OFF   16384
#define GSTG    49152
#define GEMM_SMEM (2*GSTG)   // 98304 -> 2 CTAs/SM

__device__ __forceinline__ void load_chunk(
    uint32_t base, int tid, int rowA0, int rowB0, int k0, int K,
    const __half* __restrict__ A, const __half* __restrict__ B) {
#pragma unroll
    for (int i = tid; i < 1024; i += 256) {            // A: 128 rows x 8 vec16
        int r = i >> 3, j = i & 7;
        uint32_t sw = SW128((uint32_t)((r << 7) + (j << 4)));
        CP16(base + A_OFF + sw, A + (size_t)(rowA0 + r) * K + k0 + j * 8);
    }
#pragma unroll
    for (int i = tid; i < 2048; i += 256) {            // B: 256 rows x 8 vec16
        int r = i >> 3, j = i & 7;
        uint32_t sw = SW128((uint32_t)((r << 7) + (j << 4)));
        CP16(base + B_OFF + sw, B + (size_t)(rowB0 + r) * K + k0 + j * 8);
    }
}

template <int EPI>
__global__ __launch_bounds__(256, 2)
void mma_gemm(const __half* __restrict__ A, const __half* __restrict__ B,
              const float* __restrict__ bias, const float* __restrict__ res,
              float* __restrict__ outF, __half* __restrict__ outH,
              int N, int K) {
    extern __shared__ char smem[];
    uint32_t sb = smem_u32(smem);
    int tid = threadIdx.x, wid = tid >> 5, lane = tid & 31;

    int rowA0 = blockIdx.y * GBM;
    int rowB0 = blockIdx.x * GBN;
    int warpM0 = (wid >> 2) * 64;
    int warpN0 = (wid & 3) * 64;
    const int KC = K / GBK;

    float acc[4][8][4];
#pragma unroll
    for (int i = 0; i < 4; i++)
#pragma unroll
        for (int j = 0; j < 8; j++)
#pragma unroll
            for (int r = 0; r < 4; r++) acc[i][j][r] = 0.f;

    load_chunk(sb,        tid, rowA0, rowB0, 0,   K, A, B); CPCOMMIT();
    load_chunk(sb + GSTG, tid, rowA0, rowB0, GBK, K, A, B); CPCOMMIT();

    int mat  = lane >> 3;
    int mrow = lane & 7;
    int rsel = (mat & 1) * 8 + mrow;
    int csel = mat >> 1;

    for (int c = 0; c < KC; c++) {
        uint32_t base = sb + (uint32_t)(c & 1) * GSTG;
        if (c < KC - 1) asm volatile("cp.async.wait_group 1;" ::: "memory");
        else            asm volatile("cp.async.wait_group 0;" ::: "memory");
        __syncthreads();

#pragma unroll
        for (int kk = 0; kk < 4; kk++) {
            int chunk = 2 * kk + csel;
            uint32_t ah[4][4];
#pragma unroll
            for (int mi = 0; mi < 4; mi++) {
                uint32_t sw = SW128((uint32_t)((warpM0 + mi * 16 + rsel) << 7) + (chunk << 4));
                ldmx4(ah[mi][0], ah[mi][1], ah[mi][2], ah[mi][3], base + A_OFF + sw);
            }
            uint32_t bf[8][2];
#pragma unroll
            for (int bj = 0; bj < 4; bj++) {
                uint32_t sw = SW128((uint32_t)((warpN0 + bj * 16 + rsel) << 7) + (chunk << 4));
                uint32_t r0, r1, r2, r3;
                ldmx4(r0, r1, r2, r3, base + B_OFF + sw);
                bf[2*bj][0] = r0; bf[2*bj][1] = r2; bf[2*bj+1][0] = r1; bf[2*bj+1][1] = r3;
            }
#pragma unroll
            for (int mi = 0; mi < 4; mi++)
#pragma unroll
                for (int nf = 0; nf < 8; nf++)
                    mma16816(acc[mi][nf], ah[mi], bf[nf]);
        }
        __syncthreads();
        if (c + 2 < KC) {
            load_chunk(base, tid, rowA0, rowB0, (c + 2) * GBK, K, A, B);
            CPCOMMIT();
        }
    }

    // ---------------- epilogue ----------------
    int grp = lane >> 2;
    int qd  = lane & 3;
#pragma unroll
    for (int mi = 0; mi < 4; mi++) {
#pragma unroll
        for (int half = 0; half < 2; half++) {
            int m = rowA0 + warpM0 + mi * 16 + half * 8 + grp;
            size_t orow = (size_t)m * N;
#pragma unroll
            for (int nf = 0; nf < 8; nf++) {
                int n = rowB0 + warpN0 + nf * 8 + qd * 2;
                float v0 = acc[mi][nf][half * 2 + 0];
                float v1 = acc[mi][nf][half * 2 + 1];
                if (EPI == 0) {
                    __half2 hh;
                    hh.x = __float2half_rn(v0);
                    hh.y = __float2half_rn(v1);
                    *(__half2*)(outH + orow + n) = hh;
                } else if (EPI == 2) {
                    float2 rr = *(const float2*)(res + orow + n);
                    float2 vv;
                    vv.x = v0 + bias[n]     + rr.x;
                    vv.y = v1 + bias[n + 1] + rr.y;
                    *(float2*)(outF + orow + n) = vv;
                } else {
                    v0 = fmaxf(v0 + bias[n],     0.f);
                    v1 = fmaxf(v1 + bias[n + 1], 0.f);
                    __half2 hh;
                    hh.x = __float2half_rn(v0);
                    hh.y = __float2half_rn(v1);
                    *(__half2*)(outH + orow + n) = hh;
                }
            }
        }
    }
}

// ---------------- sliding-window attention: lane-per-window ------------------
#define ATT 64
#define AROWS (ATT + 2*WINc)   // 96
#define KPITCH 66

__global__ void attn_kernel(const __half* __restrict__ qkv,
                            const int* __restrict__ mask,
                            __half* __restrict__ ao) {
    __shared__ __half sK[AROWS * KPITCH];
    __shared__ __half sV[AROWS * KPITCH];
    __shared__ float  sp[8][40];

    int bid  = blockIdx.x;
    int tile = bid & (Tc / ATT - 1);
    int h    = (bid >> 6) & (Hc - 1);
    int b    = bid >> 9;
    int t0   = tile * ATT;
    int tid  = threadIdx.x;

    for (int i = tid; i < AROWS * 32; i += 256) {
        int r = i >> 5, j = i & 31;
        int tc = t0 - WINc + r;
        uint32_t kv = 0, vv = 0;
        if (tc >= 0 && tc < Tc) {
            const __half* kr = qkv + (size_t)(b * Tc + tc) * QKVN + Ec + h * Dc;
            const __half* vr = qkv + (size_t)(b * Tc + tc) * QKVN + 2 * Ec + h * Dc;
            kv = *(const uint32_t*)(kr + j * 2);
            vv = *(const uint32_t*)(vr + j * 2);
        }
        *(uint32_t*)(sK + r * KPITCH + j * 2) = kv;
        *(uint32_t*)(sV + r * KPITCH + j * 2) = vv;
    }
    __syncthreads();

    int wid = tid >> 5, lane = tid & 31;
    for (int tt = wid; tt < ATT; tt += 8) {
        int t = t0 + tt;
        const __half2* q2 = (const __half2*)(qkv + (size_t)(b * Tc + t) * QKVN + h * Dc);

        int w  = lane;
        int tc = t + w - WINc;
        bool valid = (tc >= 0) && (tc < Tc) && (mask[b * Tc + tc] > 0);
        float s = -1e9f;
        if (valid) {
            const __half2* kr = (const __half2*)(sK + (tt + w) * KPITCH);
            float p = 0.f;
#pragma unroll
            for (int j = 0; j < 32; j++) {
                float2 qf = __half22float2(q2[j]);
                float2 kf = __half22float2(kr[j]);
                p += qf.x * kf.x + qf.y * kf.y;
            }
            s = p * 0.125f;
        }
        float s32 = -1e9f;
        {
            int tc2 = t + WINc;
            bool v2 = (tc2 < Tc) && (mask[b * Tc + tc2] > 0);
            float2 qf = __half22float2(q2[lane]);
            float2 kf = __half22float2(*(const __half2*)(sK + (tt + 32) * KPITCH + 2 * lane));
            float pp = qf.x * kf.x + qf.y * kf.y;
#pragma unroll
            for (int o = 16; o > 0; o >>= 1) pp += __shfl_xor_sync(0xffffffffu, pp, o);
            if (v2) s32 = pp * 0.125f;
        }
        float m = s;
#pragma unroll
        for (int o = 16; o > 0; o >>= 1) m = fmaxf(m, __shfl_xor_sync(0xffffffffu, m, o));
        m = fmaxf(m, s32);
        float e  = __expf(s - m);
        float es = e;
#pragma unroll
        for (int o = 16; o > 0; o >>= 1) es += __shfl_xor_sync(0xffffffffu, es, o);
        float e32 = __expf(s32 - m);
        float inv = 1.f / (es + e32);
        sp[wid][lane] = e;
        if (lane == 0) sp[wid][32] = e32;
        __syncwarp();

        float ox = 0.f, oy = 0.f;
#pragma unroll
        for (int ww = 0; ww < NW; ww++) {
            float a = sp[wid][ww];
            float2 vf = __half22float2(*(const __half2*)(sV + (tt + ww) * KPITCH + 2 * lane));
            ox += a * vf.x;
            oy += a * vf.y;
        }
        size_t ob = (size_t)(b * Tc + t) * Ec + h * Dc;
        __half2 oh;
        oh.x = __float2half_rn(ox * inv);
        oh.y = __float2half_rn(oy * inv);
        *(__half2*)(ao + ob + 2 * lane) = oh;
        __syncwarp();
    }
}

// ---------------- orchestration ----------------
extern "C" void kernel_launch(void* const* d_in, const int* in_sizes, int n_in,
                              void* d_out, int out_size) {
    const int*   tokens  = (const int*)  d_in[0];
    const int*   attmask = (const int*)  d_in[1];
    const float* tok_emb = (const float*)d_in[2];
    const float* pos_emb = (const float*)d_in[3];
    const float* Wq      = (const float*)d_in[4];
    const float* Wk      = (const float*)d_in[5];
    const float* Wv      = (const float*)d_in[6];
    const float* Wo      = (const float*)d_in[7];
    const float* bo      = (const float*)d_in[8];
    const float* ln1_g   = (const float*)d_in[9];
    const float* ln1_b   = (const float*)d_in[10];
    const float* ln2_g   = (const float*)d_in[11];
    const float* ln2_b   = (const float*)d_in[12];
    const float* W1      = (const float*)d_in[13];
    const float* b1      = (const float*)d_in[14];
    const float* W2      = (const float*)d_in[15];
    const float* b2      = (const float*)d_in[16];

    float* x = (float*)d_out;

    __half *h, *qkv, *ao, *ff, *wt;
    cudaGetSymbolAddress((void**)&h,   g_h);
    cudaGetSymbolAddress((void**)&qkv, g_qkv);
    cudaGetSymbolAddress((void**)&ao,  g_ao);
    cudaGetSymbolAddress((void**)&ff,  g_ff);
    cudaGetSymbolAddress((void**)&wt,  g_wt);

    cudaFuncSetAttribute(mma_gemm<0>, cudaFuncAttributeMaxDynamicSharedMemorySize, GEMM_SMEM);
    cudaFuncSetAttribute(mma_gemm<1>, cudaFuncAttributeMaxDynamicSharedMemorySize, GEMM_SMEM);
    cudaFuncSetAttribute(mma_gemm<2>, cudaFuncAttributeMaxDynamicSharedMemorySize, GEMM_SMEM);

    prep_kernel<<<dim3(1024, 6, Lc), dim3(32, 8)>>>(Wq, Wk, Wv, Wo, W1, W2, wt);
    embed_kernel<<<ROWS, 128>>>(tokens, tok_emb, pos_emb, x);

    for (int l = 0; l < Lc; l++) {
        const __half* w = wt + (size_t)l * WT_LAYER;

        ln_kernel<<<1024, 256>>>(x, ln1_g + l * Ec, ln1_b + l * Ec, h);

        mma_gemm<0><<<dim3(QKVN / GBN, ROWS / GBM), 256, GEMM_SMEM>>>(
            h, w + WT_QKV_OFF, nullptr, nullptr, nullptr, qkv, QKVN, Ec);

        attn_kernel<<<Bc * Hc * (Tc / ATT), 256>>>(qkv, attmask, ao);

        mma_gemm<2><<<dim3(Ec / GBN, ROWS / GBM), 256, GEMM_SMEM>>>(
            ao, w + WT_WO_OFF, bo + l * Ec, x, x, nullptr, Ec, Ec);

        ln_kernel<<<1024, 256>>>(x, ln2_g + l * Ec, ln2_b + l * Ec, h);

        mma_gemm<1><<<dim3(FFc / GBN, ROWS / GBM), 256, GEMM_SMEM>>>(
            h, w + WT_W1_OFF, b1 + l * FFc, nullptr, nullptr, ff, FFc, Ec);

        mma_gemm<2><<<dim3(Ec / GBN, ROWS / GBM), 256, GEMM_SMEM>>>(
            ff, w + WT_W2_OFF, b2 + l * Ec, x, x, nullptr, Ec, FFc);
    }
    (void)in_sizes; (void)n_in; (void)out_size;
}

// round 9
// speedup vs baseline: 2.5735x; 2.5735x over previous
#include <cuda_runtime.h>
#include <cuda_fp16.h>
#include <cstdint>

// ---------------- problem constants ----------------
#define Bc   2
#define Tc   4096
#define Ec   512
#define Hc   8
#define Dc   64
#define FFc  2048
#define Lc   2
#define WINc 16
#define NW   33
#define ROWS (Bc*Tc)      // 8192
#define EPSc 1e-5f
#define QKVN (3*Ec)       // 1536

#define WT_QKV_OFF 0
#define WT_WO_OFF  (3*Ec*Ec)
#define WT_W1_OFF  (4*Ec*Ec)
#define WT_W2_OFF  (WT_W1_OFF + FFc*Ec)
#define WT_LAYER   (WT_W2_OFF + Ec*FFc)

// ---------------- scratch ----------------
__device__ __half g_h   [(size_t)ROWS*Ec];
__device__ __half g_qkv [(size_t)ROWS*QKVN];
__device__ __half g_ao  [(size_t)ROWS*Ec];
__device__ __half g_ff  [(size_t)ROWS*FFc];
__device__ __half g_wt  [(size_t)Lc*WT_LAYER];

// ---------------- helpers ----------------
__device__ __forceinline__ uint32_t smem_u32(const void* p) {
    uint32_t a;
    asm("{ .reg .u64 t; cvta.to.shared.u64 t, %1; cvt.u32.u64 %0, t; }" : "=r"(a) : "l"(p));
    return a;
}
#define SW128(x) ((x) ^ (((x) >> 3) & 0x70))

#define CP16(dst, src) \
    asm volatile("cp.async.cg.shared.global [%0], [%1], 16;" :: "r"(dst), "l"(src) : "memory")
#define CPCOMMIT() asm volatile("cp.async.commit_group;" ::: "memory")

__device__ __forceinline__ void ldmx4(uint32_t& r0, uint32_t& r1, uint32_t& r2, uint32_t& r3,
                                      uint32_t addr) {
    asm volatile("ldmatrix.sync.aligned.m8n8.x4.shared.b16 {%0,%1,%2,%3}, [%4];"
                 : "=r"(r0), "=r"(r1), "=r"(r2), "=r"(r3) : "r"(addr));
}
__device__ __forceinline__ void mma16816(float* c, const uint32_t* a, const uint32_t* b) {
    asm volatile("mma.sync.aligned.m16n8k16.row.col.f32.f16.f16.f32 "
                 "{%0,%1,%2,%3}, {%4,%5,%6,%7}, {%8,%9}, {%0,%1,%2,%3};"
                 : "+f"(c[0]), "+f"(c[1]), "+f"(c[2]), "+f"(c[3])
                 : "r"(a[0]), "r"(a[1]), "r"(a[2]), "r"(a[3]), "r"(b[0]), "r"(b[1]));
}

// ---------------- embedding ----------------
__global__ void embed_kernel(const int* __restrict__ tokens,
                             const float* __restrict__ tok_emb,
                             const float* __restrict__ pos_emb,
                             float* __restrict__ x) {
    int row = blockIdx.x;
    int t   = row & (Tc - 1);
    int tok = tokens[row];
    int e   = threadIdx.x * 4;
    float4 a = *(const float4*)(tok_emb + (size_t)tok * Ec + e);
    float4 p = *(const float4*)(pos_emb + (size_t)t   * Ec + e);
    a.x += p.x; a.y += p.y; a.z += p.z; a.w += p.w;
    *(float4*)(x + (size_t)row * Ec + e) = a;
}

// ---------------- layernorm -> fp16 ----------------
__global__ void ln_kernel(const float* __restrict__ x,
                          const float* __restrict__ g,
                          const float* __restrict__ b,
                          __half* __restrict__ y) {
    int warp = (blockIdx.x * blockDim.x + threadIdx.x) >> 5;
    int lane = threadIdx.x & 31;
    if (warp >= ROWS) return;
    const float* xr = x + (size_t)warp * Ec;
    float v[16];
    float s = 0.f;
#pragma unroll
    for (int i = 0; i < 16; i++) { v[i] = xr[lane + i * 32]; s += v[i]; }
#pragma unroll
    for (int o = 16; o > 0; o >>= 1) s += __shfl_xor_sync(0xffffffffu, s, o);
    float mean = s * (1.f / Ec);
    float ss = 0.f;
#pragma unroll
    for (int i = 0; i < 16; i++) { float d = v[i] - mean; ss += d * d; }
#pragma unroll
    for (int o = 16; o > 0; o >>= 1) ss += __shfl_xor_sync(0xffffffffu, ss, o);
    float inv = rsqrtf(ss * (1.f / Ec) + EPSc);
    size_t rb = (size_t)warp * Ec;
#pragma unroll
    for (int i = 0; i < 16; i++) {
        int idx = lane + i * 32;
        y[rb + idx] = __float2half_rn((v[i] - mean) * inv * g[idx] + b[idx]);
    }
}

// ---------------- fused weight prep (fp16 transpose) ----------------
__global__ void prep_kernel(const float* __restrict__ Wq, const float* __restrict__ Wk,
                            const float* __restrict__ Wv, const float* __restrict__ Wo,
                            const float* __restrict__ W1, const float* __restrict__ W2,
                            __half* __restrict__ thi) {
    int l = blockIdx.z, y = blockIdx.y;
    int K = (y == 5) ? FFc : Ec;
    int N = (y == 4) ? FFc : Ec;
    int ntiles = N >> 5;
    int nt = blockIdx.x % ntiles;
    int kt = blockIdx.x / ntiles;
    if (kt >= (K >> 5)) return;

    const float* W; size_t doff;
    switch (y) {
        case 0: W = Wq + (size_t)l * Ec * Ec;  doff = WT_QKV_OFF;            break;
        case 1: W = Wk + (size_t)l * Ec * Ec;  doff = WT_QKV_OFF + Ec * Ec;  break;
        case 2: W = Wv + (size_t)l * Ec * Ec;  doff = WT_QKV_OFF + 2*Ec*Ec;  break;
        case 3: W = Wo + (size_t)l * Ec * Ec;  doff = WT_WO_OFF;             break;
        case 4: W = W1 + (size_t)l * Ec * FFc; doff = WT_W1_OFF;             break;
        default:W = W2 + (size_t)l * FFc * Ec; doff = WT_W2_OFF;             break;
    }
    doff += (size_t)l * WT_LAYER;

    __shared__ float tile[32][33];
    int n0 = nt * 32, k0 = kt * 32;
    int tx = threadIdx.x, ty = threadIdx.y;
#pragma unroll
    for (int i = 0; i < 32; i += 8)
        tile[ty + i][tx] = W[(size_t)(k0 + ty + i) * N + n0 + tx];
    __syncthreads();
#pragma unroll
    for (int i = 0; i < 32; i += 8) {
        float v = tile[tx][ty + i];
        thi[doff + (size_t)(n0 + ty + i) * K + k0 + tx] = __float2half_rn(v);
    }
}

// ---------------- mma.sync GEMM: CTA 128x256, warp 64x64, single fp16 pass ---
// EPI: 0 = fp16 out; 1 = bias+relu -> fp16; 2 = bias+residual fp32
#define GBM 128
#define GBN 256
#define GBK 64
#define A_OFF   0
#define B_OFF   16384
#define GSTG    49152
#define NSTAGE  3
#define GEMM_SMEM (NSTAGE*GSTG)   // 147456, 1 CTA/SM (regs preclude 2 anyway)

__device__ __forceinline__ void load_chunk(
    uint32_t base, int tid, int rowA0, int rowB0, int k0, int K,
    const __half* __restrict__ A, const __half* __restrict__ B) {
#pragma unroll
    for (int i = tid; i < 1024; i += 256) {            // A: 128 rows x 8 vec16
        int r = i >> 3, j = i & 7;
        uint32_t sw = SW128((uint32_t)((r << 7) + (j << 4)));
        CP16(base + A_OFF + sw, A + (size_t)(rowA0 + r) * K + k0 + j * 8);
    }
#pragma unroll
    for (int i = tid; i < 2048; i += 256) {            // B: 256 rows x 8 vec16
        int r = i >> 3, j = i & 7;
        uint32_t sw = SW128((uint32_t)((r << 7) + (j << 4)));
        CP16(base + B_OFF + sw, B + (size_t)(rowB0 + r) * K + k0 + j * 8);
    }
}

template <int EPI>
__global__ __launch_bounds__(256, 1)
void mma_gemm(const __half* __restrict__ A, const __half* __restrict__ B,
              const float* __restrict__ bias, const float* __restrict__ res,
              float* __restrict__ outF, __half* __restrict__ outH,
              int N, int K) {
    extern __shared__ char smem[];
    uint32_t sb = smem_u32(smem);
    int tid = threadIdx.x, wid = tid >> 5, lane = tid & 31;

    int rowA0 = blockIdx.y * GBM;
    int rowB0 = blockIdx.x * GBN;
    int warpM0 = (wid >> 2) * 64;
    int warpN0 = (wid & 3) * 64;
    const int KC = K / GBK;

    float acc[4][8][4];
#pragma unroll
    for (int i = 0; i < 4; i++)
#pragma unroll
        for (int j = 0; j < 8; j++)
#pragma unroll
            for (int r = 0; r < 4; r++) acc[i][j][r] = 0.f;

    load_chunk(sb,        tid, rowA0, rowB0, 0,   K, A, B); CPCOMMIT();
    load_chunk(sb + GSTG, tid, rowA0, rowB0, GBK, K, A, B); CPCOMMIT();

    int mat  = lane >> 3;
    int mrow = lane & 7;
    int rsel = (mat & 1) * 8 + mrow;
    int csel = mat >> 1;

    for (int c = 0; c < KC; c++) {
        uint32_t base = sb + (uint32_t)(c % NSTAGE) * GSTG;
        // stage c must be resident: newer-than-c groups in flight = 1 except last iter
        if (c < KC - 1) asm volatile("cp.async.wait_group 1;" ::: "memory");
        else            asm volatile("cp.async.wait_group 0;" ::: "memory");
        __syncthreads();
        if (c + 2 < KC) {   // prefetch into stage (c+2)%3 (consumed at iter c-1, sync'd)
            load_chunk(sb + (uint32_t)((c + 2) % NSTAGE) * GSTG,
                       tid, rowA0, rowB0, (c + 2) * GBK, K, A, B);
            CPCOMMIT();
        }

#pragma unroll
        for (int kk = 0; kk < 4; kk++) {
            int chunk = 2 * kk + csel;
            uint32_t ah[4][4];
#pragma unroll
            for (int mi = 0; mi < 4; mi++) {
                uint32_t sw = SW128((uint32_t)((warpM0 + mi * 16 + rsel) << 7) + (chunk << 4));
                ldmx4(ah[mi][0], ah[mi][1], ah[mi][2], ah[mi][3], base + A_OFF + sw);
            }
            uint32_t bf[8][2];
#pragma unroll
            for (int bj = 0; bj < 4; bj++) {
                uint32_t sw = SW128((uint32_t)((warpN0 + bj * 16 + rsel) << 7) + (chunk << 4));
                uint32_t r0, r1, r2, r3;
                ldmx4(r0, r1, r2, r3, base + B_OFF + sw);
                bf[2*bj][0] = r0; bf[2*bj][1] = r2; bf[2*bj+1][0] = r1; bf[2*bj+1][1] = r3;
            }
#pragma unroll
            for (int mi = 0; mi < 4; mi++)
#pragma unroll
                for (int nf = 0; nf < 8; nf++)
                    mma16816(acc[mi][nf], ah[mi], bf[nf]);
        }
        __syncthreads();   // all warps done with stage c before it is refilled
    }

    // ---------------- epilogue ----------------
    int grp = lane >> 2;
    int qd  = lane & 3;
#pragma unroll
    for (int mi = 0; mi < 4; mi++) {
#pragma unroll
        for (int half = 0; half < 2; half++) {
            int m = rowA0 + warpM0 + mi * 16 + half * 8 + grp;
            size_t orow = (size_t)m * N;
#pragma unroll
            for (int nf = 0; nf < 8; nf++) {
                int n = rowB0 + warpN0 + nf * 8 + qd * 2;
                float v0 = acc[mi][nf][half * 2 + 0];
                float v1 = acc[mi][nf][half * 2 + 1];
                if (EPI == 0) {
                    __half2 hh;
                    hh.x = __float2half_rn(v0);
                    hh.y = __float2half_rn(v1);
                    *(__half2*)(outH + orow + n) = hh;
                } else if (EPI == 2) {
                    float2 rr = *(const float2*)(res + orow + n);
                    float2 vv;
                    vv.x = v0 + bias[n]     + rr.x;
                    vv.y = v1 + bias[n + 1] + rr.y;
                    *(float2*)(outF + orow + n) = vv;
                } else {
                    v0 = fmaxf(v0 + bias[n],     0.f);
                    v1 = fmaxf(v1 + bias[n + 1], 0.f);
                    __half2 hh;
                    hh.x = __float2half_rn(v0);
                    hh.y = __float2half_rn(v1);
                    *(__half2*)(outH + orow + n) = hh;
                }
            }
        }
    }
}

// ---------------- sliding-window attention: lane-per-window ------------------
#define ATT 64
#define AROWS (ATT + 2*WINc)   // 96
#define KPITCH 66

__global__ void attn_kernel(const __half* __restrict__ qkv,
                            const int* __restrict__ mask,
                            __half* __restrict__ ao) {
    __shared__ __half sK[AROWS * KPITCH];
    __shared__ __half sV[AROWS * KPITCH];
    __shared__ float  sp[8][40];

    int bid  = blockIdx.x;
    int tile = bid & (Tc / ATT - 1);
    int h    = (bid >> 6) & (Hc - 1);
    int b    = bid >> 9;
    int t0   = tile * ATT;
    int tid  = threadIdx.x;

    for (int i = tid; i < AROWS * 32; i += 256) {
        int r = i >> 5, j = i & 31;
        int tc = t0 - WINc + r;
        uint32_t kv = 0, vv = 0;
        if (tc >= 0 && tc < Tc) {
            const __half* kr = qkv + (size_t)(b * Tc + tc) * QKVN + Ec + h * Dc;
            const __half* vr = qkv + (size_t)(b * Tc + tc) * QKVN + 2 * Ec + h * Dc;
            kv = *(const uint32_t*)(kr + j * 2);
            vv = *(const uint32_t*)(vr + j * 2);
        }
        *(uint32_t*)(sK + r * KPITCH + j * 2) = kv;
        *(uint32_t*)(sV + r * KPITCH + j * 2) = vv;
    }
    __syncthreads();

    int wid = tid >> 5, lane = tid & 31;
    for (int tt = wid; tt < ATT; tt += 8) {
        int t = t0 + tt;
        const __half2* q2 = (const __half2*)(qkv + (size_t)(b * Tc + t) * QKVN + h * Dc);

        int w  = lane;
        int tc = t + w - WINc;
        bool valid = (tc >= 0) && (tc < Tc) && (mask[b * Tc + tc] > 0);
        float s = -1e9f;
        if (valid) {
            const __half2* kr = (const __half2*)(sK + (tt + w) * KPITCH);
            float p = 0.f;
#pragma unroll
            for (int j = 0; j < 32; j++) {
                float2 qf = __half22float2(q2[j]);
                float2 kf = __half22float2(kr[j]);
                p += qf.x * kf.x + qf.y * kf.y;
            }
            s = p * 0.125f;
        }
        float s32 = -1e9f;
        {
            int tc2 = t + WINc;
            bool v2 = (tc2 < Tc) && (mask[b * Tc + tc2] > 0);
            float2 qf = __half22float2(q2[lane]);
            float2 kf = __half22float2(*(const __half2*)(sK + (tt + 32) * KPITCH + 2 * lane));
            float pp = qf.x * kf.x + qf.y * kf.y;
#pragma unroll
            for (int o = 16; o > 0; o >>= 1) pp += __shfl_xor_sync(0xffffffffu, pp, o);
            if (v2) s32 = pp * 0.125f;
        }
        float m = s;
#pragma unroll
        for (int o = 16; o > 0; o >>= 1) m = fmaxf(m, __shfl_xor_sync(0xffffffffu, m, o));
        m = fmaxf(m, s32);
        float e  = __expf(s - m);
        float es = e;
#pragma unroll
        for (int o = 16; o > 0; o >>= 1) es += __shfl_xor_sync(0xffffffffu, es, o);
        float e32 = __expf(s32 - m);
        float inv = 1.f / (es + e32);
        sp[wid][lane] = e;
        if (lane == 0) sp[wid][32] = e32;
        __syncwarp();

        float ox = 0.f, oy = 0.f;
#pragma unroll
        for (int ww = 0; ww < NW; ww++) {
            float a = sp[wid][ww];
            float2 vf = __half22float2(*(const __half2*)(sV + (tt + ww) * KPITCH + 2 * lane));
            ox += a * vf.x;
            oy += a * vf.y;
        }
        size_t ob = (size_t)(b * Tc + t) * Ec + h * Dc;
        __half2 oh;
        oh.x = __float2half_rn(ox * inv);
        oh.y = __float2half_rn(oy * inv);
        *(__half2*)(ao + ob + 2 * lane) = oh;
        __syncwarp();
    }
}

// ---------------- orchestration ----------------
extern "C" void kernel_launch(void* const* d_in, const int* in_sizes, int n_in,
                              void* d_out, int out_size) {
    const int*   tokens  = (const int*)  d_in[0];
    const int*   attmask = (const int*)  d_in[1];
    const float* tok_emb = (const float*)d_in[2];
    const float* pos_emb = (const float*)d_in[3];
    const float* Wq      = (const float*)d_in[4];
    const float* Wk      = (const float*)d_in[5];
    const float* Wv      = (const float*)d_in[6];
    const float* Wo      = (const float*)d_in[7];
    const float* bo      = (const float*)d_in[8];
    const float* ln1_g   = (const float*)d_in[9];
    const float* ln1_b   = (const float*)d_in[10];
    const float* ln2_g   = (const float*)d_in[11];
    const float* ln2_b   = (const float*)d_in[12];
    const float* W1      = (const float*)d_in[13];
    const float* b1      = (const float*)d_in[14];
    const float* W2      = (const float*)d_in[15];
    const float* b2      = (const float*)d_in[16];

    float* x = (float*)d_out;

    __half *h, *qkv, *ao, *ff, *wt;
    cudaGetSymbolAddress((void**)&h,   g_h);
    cudaGetSymbolAddress((void**)&qkv, g_qkv);
    cudaGetSymbolAddress((void**)&ao,  g_ao);
    cudaGetSymbolAddress((void**)&ff,  g_ff);
    cudaGetSymbolAddress((void**)&wt,  g_wt);

    cudaFuncSetAttribute(mma_gemm<0>, cudaFuncAttributeMaxDynamicSharedMemorySize, GEMM_SMEM);
    cudaFuncSetAttribute(mma_gemm<1>, cudaFuncAttributeMaxDynamicSharedMemorySize, GEMM_SMEM);
    cudaFuncSetAttribute(mma_gemm<2>, cudaFuncAttributeMaxDynamicSharedMemorySize, GEMM_SMEM);

    prep_kernel<<<dim3(1024, 6, Lc), dim3(32, 8)>>>(Wq, Wk, Wv, Wo, W1, W2, wt);
    embed_kernel<<<ROWS, 128>>>(tokens, tok_emb, pos_emb, x);

    for (int l = 0; l < Lc; l++) {
        const __half* w = wt + (size_t)l * WT_LAYER;

        ln_kernel<<<1024, 256>>>(x, ln1_g + l * Ec, ln1_b + l * Ec, h);

        mma_gemm<0><<<dim3(QKVN / GBN, ROWS / GBM), 256, GEMM_SMEM>>>(
            h, w + WT_QKV_OFF, nullptr, nullptr, nullptr, qkv, QKVN, Ec);

        attn_kernel<<<Bc * Hc * (Tc / ATT), 256>>>(qkv, attmask, ao);

        mma_gemm<2><<<dim3(Ec / GBN, ROWS / GBM), 256, GEMM_SMEM>>>(
            ao, w + WT_WO_OFF, bo + l * Ec, x, x, nullptr, Ec, Ec);

        ln_kernel<<<1024, 256>>>(x, ln2_g + l * Ec, ln2_b + l * Ec, h);

        mma_gemm<1><<<dim3(FFc / GBN, ROWS / GBM), 256, GEMM_SMEM>>>(
            h, w + WT_W1_OFF, b1 + l * FFc, nullptr, nullptr, ff, FFc, Ec);

        mma_gemm<2><<<dim3(Ec / GBN, ROWS / GBM), 256, GEMM_SMEM>>>(
            ff, w + WT_W2_OFF, b2 + l * Ec, x, x, nullptr, Ec, FFc);
    }
    (void)in_sizes; (void)n_in; (void)out_size;
}

// round 10
// speedup vs baseline: 2.6540x; 1.0313x over previous
#include <cuda_runtime.h>
#include <cuda_fp16.h>
#include <cstdint>

// ---------------- problem constants ----------------
#define Bc   2
#define Tc   4096
#define Ec   512
#define Hc   8
#define Dc   64
#define FFc  2048
#define Lc   2
#define WINc 16
#define NW   33
#define ROWS (Bc*Tc)      // 8192
#define EPSc 1e-5f
#define QKVN (3*Ec)       // 1536

#define WT_QKV_OFF 0
#define WT_WO_OFF  (3*Ec*Ec)
#define WT_W1_OFF  (4*Ec*Ec)
#define WT_W2_OFF  (WT_W1_OFF + FFc*Ec)
#define WT_LAYER   (WT_W2_OFF + Ec*FFc)

// ---------------- scratch ----------------
__device__ __half g_h   [(size_t)ROWS*Ec];
__device__ __half g_qkv [(size_t)ROWS*QKVN];
__device__ __half g_ao  [(size_t)ROWS*Ec];
__device__ __half g_ff  [(size_t)ROWS*FFc];
__device__ __half g_wt  [(size_t)Lc*WT_LAYER];

// ---------------- helpers ----------------
__device__ __forceinline__ uint32_t smem_u32(const void* p) {
    uint32_t a;
    asm("{ .reg .u64 t; cvta.to.shared.u64 t, %1; cvt.u32.u64 %0, t; }" : "=r"(a) : "l"(p));
    return a;
}
#define SW128(x) ((x) ^ (((x) >> 3) & 0x70))

#define CP16(dst, src) \
    asm volatile("cp.async.cg.shared.global [%0], [%1], 16;" :: "r"(dst), "l"(src) : "memory")
#define CPCOMMIT() asm volatile("cp.async.commit_group;" ::: "memory")

__device__ __forceinline__ void ldmx4(uint32_t& r0, uint32_t& r1, uint32_t& r2, uint32_t& r3,
                                      uint32_t addr) {
    asm volatile("ldmatrix.sync.aligned.m8n8.x4.shared.b16 {%0,%1,%2,%3}, [%4];"
                 : "=r"(r0), "=r"(r1), "=r"(r2), "=r"(r3) : "r"(addr));
}
__device__ __forceinline__ void mma16816(float* c, const uint32_t* a, const uint32_t* b) {
    asm volatile("mma.sync.aligned.m16n8k16.row.col.f32.f16.f16.f32 "
                 "{%0,%1,%2,%3}, {%4,%5,%6,%7}, {%8,%9}, {%0,%1,%2,%3};"
                 : "+f"(c[0]), "+f"(c[1]), "+f"(c[2]), "+f"(c[3])
                 : "r"(a[0]), "r"(a[1]), "r"(a[2]), "r"(a[3]), "r"(b[0]), "r"(b[1]));
}

// ---------------- embedding ----------------
__global__ void embed_kernel(const int* __restrict__ tokens,
                             const float* __restrict__ tok_emb,
                             const float* __restrict__ pos_emb,
                             float* __restrict__ x) {
    int row = blockIdx.x;
    int t   = row & (Tc - 1);
    int tok = tokens[row];
    int e   = threadIdx.x * 4;
    float4 a = *(const float4*)(tok_emb + (size_t)tok * Ec + e);
    float4 p = *(const float4*)(pos_emb + (size_t)t   * Ec + e);
    a.x += p.x; a.y += p.y; a.z += p.z; a.w += p.w;
    *(float4*)(x + (size_t)row * Ec + e) = a;
}

// ---------------- layernorm -> fp16 ----------------
__global__ void ln_kernel(const float* __restrict__ x,
                          const float* __restrict__ g,
                          const float* __restrict__ b,
                          __half* __restrict__ y) {
    int warp = (blockIdx.x * blockDim.x + threadIdx.x) >> 5;
    int lane = threadIdx.x & 31;
    if (warp >= ROWS) return;
    const float* xr = x + (size_t)warp * Ec;
    float v[16];
    float s = 0.f;
#pragma unroll
    for (int i = 0; i < 16; i++) { v[i] = xr[lane + i * 32]; s += v[i]; }
#pragma unroll
    for (int o = 16; o > 0; o >>= 1) s += __shfl_xor_sync(0xffffffffu, s, o);
    float mean = s * (1.f / Ec);
    float ss = 0.f;
#pragma unroll
    for (int i = 0; i < 16; i++) { float d = v[i] - mean; ss += d * d; }
#pragma unroll
    for (int o = 16; o > 0; o >>= 1) ss += __shfl_xor_sync(0xffffffffu, ss, o);
    float inv = rsqrtf(ss * (1.f / Ec) + EPSc);
    size_t rb = (size_t)warp * Ec;
#pragma unroll
    for (int i = 0; i < 16; i++) {
        int idx = lane + i * 32;
        y[rb + idx] = __float2half_rn((v[i] - mean) * inv * g[idx] + b[idx]);
    }
}

// ---------------- fused weight prep (fp16 transpose) ----------------
__global__ void prep_kernel(const float* __restrict__ Wq, const float* __restrict__ Wk,
                            const float* __restrict__ Wv, const float* __restrict__ Wo,
                            const float* __restrict__ W1, const float* __restrict__ W2,
                            __half* __restrict__ thi) {
    int l = blockIdx.z, y = blockIdx.y;
    int K = (y == 5) ? FFc : Ec;
    int N = (y == 4) ? FFc : Ec;
    int ntiles = N >> 5;
    int nt = blockIdx.x % ntiles;
    int kt = blockIdx.x / ntiles;
    if (kt >= (K >> 5)) return;

    const float* W; size_t doff;
    switch (y) {
        case 0: W = Wq + (size_t)l * Ec * Ec;  doff = WT_QKV_OFF;            break;
        case 1: W = Wk + (size_t)l * Ec * Ec;  doff = WT_QKV_OFF + Ec * Ec;  break;
        case 2: W = Wv + (size_t)l * Ec * Ec;  doff = WT_QKV_OFF + 2*Ec*Ec;  break;
        case 3: W = Wo + (size_t)l * Ec * Ec;  doff = WT_WO_OFF;             break;
        case 4: W = W1 + (size_t)l * Ec * FFc; doff = WT_W1_OFF;             break;
        default:W = W2 + (size_t)l * FFc * Ec; doff = WT_W2_OFF;             break;
    }
    doff += (size_t)l * WT_LAYER;

    __shared__ float tile[32][33];
    int n0 = nt * 32, k0 = kt * 32;
    int tx = threadIdx.x, ty = threadIdx.y;
#pragma unroll
    for (int i = 0; i < 32; i += 8)
        tile[ty + i][tx] = W[(size_t)(k0 + ty + i) * N + n0 + tx];
    __syncthreads();
#pragma unroll
    for (int i = 0; i < 32; i += 8) {
        float v = tile[tx][ty + i];
        thi[doff + (size_t)(n0 + ty + i) * K + k0 + tx] = __float2half_rn(v);
    }
}

// ---------------- mma.sync GEMM: CTA 128x256, warp 64x64, paired chunks ------
// Single fp16 pass; barrier per 128-K pair (4 blocks of 48KB, 2-pair pipeline)
// EPI: 0 = fp16 out; 1 = bias+relu -> fp16; 2 = bias+residual fp32
#define GBM 128
#define GBN 256
#define GBK 64
#define A_OFF   0
#define B_OFF   16384
#define GSTG    49152
#define GEMM_SMEM (4*GSTG)   // 196608: 4 blocks = 2 pairs

__device__ __forceinline__ void load_chunk(
    uint32_t base, int tid, int rowA0, int rowB0, int k0, int K,
    const __half* __restrict__ A, const __half* __restrict__ B) {
#pragma unroll
    for (int i = tid; i < 1024; i += 256) {            // A: 128 rows x 8 vec16
        int r = i >> 3, j = i & 7;
        uint32_t sw = SW128((uint32_t)((r << 7) + (j << 4)));
        CP16(base + A_OFF + sw, A + (size_t)(rowA0 + r) * K + k0 + j * 8);
    }
#pragma unroll
    for (int i = tid; i < 2048; i += 256) {            // B: 256 rows x 8 vec16
        int r = i >> 3, j = i & 7;
        uint32_t sw = SW128((uint32_t)((r << 7) + (j << 4)));
        CP16(base + B_OFF + sw, B + (size_t)(rowB0 + r) * K + k0 + j * 8);
    }
}

template <int EPI>
__global__ __launch_bounds__(256, 1)
void mma_gemm(const __half* __restrict__ A, const __half* __restrict__ B,
              const float* __restrict__ bias, const float* __restrict__ res,
              float* __restrict__ outF, __half* __restrict__ outH,
              int N, int K) {
    extern __shared__ char smem[];
    uint32_t sb = smem_u32(smem);
    int tid = threadIdx.x, wid = tid >> 5, lane = tid & 31;

    int rowA0 = blockIdx.y * GBM;
    int rowB0 = blockIdx.x * GBN;
    int warpM0 = (wid >> 2) * 64;
    int warpN0 = (wid & 3) * 64;
    const int PC = K / (2 * GBK);   // pairs of 64-K chunks

    float acc[4][8][4];
#pragma unroll
    for (int i = 0; i < 4; i++)
#pragma unroll
        for (int j = 0; j < 8; j++)
#pragma unroll
            for (int r = 0; r < 4; r++) acc[i][j][r] = 0.f;

    // prologue: both pairs (4 blocks), one commit group per pair
    load_chunk(sb,            tid, rowA0, rowB0, 0 * GBK, K, A, B);
    load_chunk(sb + GSTG,     tid, rowA0, rowB0, 1 * GBK, K, A, B); CPCOMMIT();
    load_chunk(sb + 2 * GSTG, tid, rowA0, rowB0, 2 * GBK, K, A, B);
    load_chunk(sb + 3 * GSTG, tid, rowA0, rowB0, 3 * GBK, K, A, B); CPCOMMIT();

    int mat  = lane >> 3;
    int mrow = lane & 7;
    int rsel = (mat & 1) * 8 + mrow;
    int csel = mat >> 1;

    for (int p = 0; p < PC; p++) {
        uint32_t pb = sb + (uint32_t)((2 * p) & 3) * GSTG;  // pair base: blocks {0,1} or {2,3}
        if (p < PC - 1) asm volatile("cp.async.wait_group 1;" ::: "memory");
        else            asm volatile("cp.async.wait_group 0;" ::: "memory");
        __syncthreads();

#pragma unroll
        for (int half = 0; half < 2; half++) {
            uint32_t base = pb + (uint32_t)half * GSTG;
#pragma unroll
            for (int kk = 0; kk < 4; kk++) {
                int chunk = 2 * kk + csel;
                uint32_t ah[4][4];
#pragma unroll
                for (int mi = 0; mi < 4; mi++) {
                    uint32_t sw = SW128((uint32_t)((warpM0 + mi * 16 + rsel) << 7) + (chunk << 4));
                    ldmx4(ah[mi][0], ah[mi][1], ah[mi][2], ah[mi][3], base + A_OFF + sw);
                }
                uint32_t bf[8][2];
#pragma unroll
                for (int bj = 0; bj < 4; bj++) {
                    uint32_t sw = SW128((uint32_t)((warpN0 + bj * 16 + rsel) << 7) + (chunk << 4));
                    uint32_t r0, r1, r2, r3;
                    ldmx4(r0, r1, r2, r3, base + B_OFF + sw);
                    bf[2*bj][0] = r0; bf[2*bj][1] = r2; bf[2*bj+1][0] = r1; bf[2*bj+1][1] = r3;
                }
#pragma unroll
                for (int mi = 0; mi < 4; mi++)
#pragma unroll
                    for (int nf = 0; nf < 8; nf++)
                        mma16816(acc[mi][nf], ah[mi], bf[nf]);
            }
        }
        __syncthreads();   // pair p fully consumed by all warps before refill
        if (p + 2 < PC) {
            load_chunk(pb,        tid, rowA0, rowB0, (2 * p + 4) * GBK, K, A, B);
            load_chunk(pb + GSTG, tid, rowA0, rowB0, (2 * p + 5) * GBK, K, A, B);
            CPCOMMIT();
        }
    }

    // ---------------- epilogue ----------------
    int grp = lane >> 2;
    int qd  = lane & 3;
#pragma unroll
    for (int mi = 0; mi < 4; mi++) {
#pragma unroll
        for (int half = 0; half < 2; half++) {
            int m = rowA0 + warpM0 + mi * 16 + half * 8 + grp;
            size_t orow = (size_t)m * N;
#pragma unroll
            for (int nf = 0; nf < 8; nf++) {
                int n = rowB0 + warpN0 + nf * 8 + qd * 2;
                float v0 = acc[mi][nf][half * 2 + 0];
                float v1 = acc[mi][nf][half * 2 + 1];
                if (EPI == 0) {
                    __half2 hh;
                    hh.x = __float2half_rn(v0);
                    hh.y = __float2half_rn(v1);
                    *(__half2*)(outH + orow + n) = hh;
                } else if (EPI == 2) {
                    float2 rr = *(const float2*)(res + orow + n);
                    float2 vv;
                    vv.x = v0 + bias[n]     + rr.x;
                    vv.y = v1 + bias[n + 1] + rr.y;
                    *(float2*)(outF + orow + n) = vv;
                } else {
                    v0 = fmaxf(v0 + bias[n],     0.f);
                    v1 = fmaxf(v1 + bias[n + 1], 0.f);
                    __half2 hh;
                    hh.x = __float2half_rn(v0);
                    hh.y = __float2half_rn(v1);
                    *(__half2*)(outH + orow + n) = hh;
                }
            }
        }
    }
}

// ---------------- sliding-window attention: lane-per-window ------------------
#define ATT 64
#define AROWS (ATT + 2*WINc)   // 96
#define KPITCH 66

__global__ void attn_kernel(const __half* __restrict__ qkv,
                            const int* __restrict__ mask,
                            __half* __restrict__ ao) {
    __shared__ __half sK[AROWS * KPITCH];
    __shared__ __half sV[AROWS * KPITCH];
    __shared__ float  sp[8][40];
    __shared__ int    sM[AROWS];

    int bid  = blockIdx.x;
    int tile = bid & (Tc / ATT - 1);
    int h    = (bid >> 6) & (Hc - 1);
    int b    = bid >> 9;
    int t0   = tile * ATT;
    int tid  = threadIdx.x;

    if (tid < AROWS) {
        int tc = t0 - WINc + tid;
        sM[tid] = (tc >= 0 && tc < Tc) ? mask[b * Tc + tc] : 0;
    }
    for (int i = tid; i < AROWS * 32; i += 256) {
        int r = i >> 5, j = i & 31;
        int tc = t0 - WINc + r;
        uint32_t kv = 0, vv = 0;
        if (tc >= 0 && tc < Tc) {
            const __half* kr = qkv + (size_t)(b * Tc + tc) * QKVN + Ec + h * Dc;
            const __half* vr = qkv + (size_t)(b * Tc + tc) * QKVN + 2 * Ec + h * Dc;
            kv = *(const uint32_t*)(kr + j * 2);
            vv = *(const uint32_t*)(vr + j * 2);
        }
        *(uint32_t*)(sK + r * KPITCH + j * 2) = kv;
        *(uint32_t*)(sV + r * KPITCH + j * 2) = vv;
    }
    __syncthreads();

    int wid = tid >> 5, lane = tid & 31;
    for (int tt = wid; tt < ATT; tt += 8) {
        int t = t0 + tt;
        const __half2* q2 = (const __half2*)(qkv + (size_t)(b * Tc + t) * QKVN + h * Dc);

        int w = lane;
        bool valid = sM[tt + w] > 0;
        float s = -1e9f;
        if (valid) {
            const __half2* kr = (const __half2*)(sK + (tt + w) * KPITCH);
            float p = 0.f;
#pragma unroll
            for (int j = 0; j < 32; j++) {
                float2 qf = __half22float2(q2[j]);
                float2 kf = __half22float2(kr[j]);
                p += qf.x * kf.x + qf.y * kf.y;
            }
            s = p * 0.125f;
        }
        float s32 = -1e9f;
        {
            bool v2 = sM[tt + 32] > 0;
            float2 qf = __half22float2(q2[lane]);
            float2 kf = __half22float2(*(const __half2*)(sK + (tt + 32) * KPITCH + 2 * lane));
            float pp = qf.x * kf.x + qf.y * kf.y;
#pragma unroll
            for (int o = 16; o > 0; o >>= 1) pp += __shfl_xor_sync(0xffffffffu, pp, o);
            if (v2) s32 = pp * 0.125f;
        }
        float m = s;
#pragma unroll
        for (int o = 16; o > 0; o >>= 1) m = fmaxf(m, __shfl_xor_sync(0xffffffffu, m, o));
        m = fmaxf(m, s32);
        float e  = __expf(s - m);
        float es = e;
#pragma unroll
        for (int o = 16; o > 0; o >>= 1) es += __shfl_xor_sync(0xffffffffu, es, o);
        float e32 = __expf(s32 - m);
        float inv = 1.f / (es + e32);
        sp[wid][lane] = e;
        if (lane == 0) sp[wid][32] = e32;
        __syncwarp();

        float ox = 0.f, oy = 0.f;
#pragma unroll
        for (int ww = 0; ww < NW; ww++) {
            float a = sp[wid][ww];
            float2 vf = __half22float2(*(const __half2*)(sV + (tt + ww) * KPITCH + 2 * lane));
            ox += a * vf.x;
            oy += a * vf.y;
        }
        size_t ob = (size_t)(b * Tc + t) * Ec + h * Dc;
        __half2 oh;
        oh.x = __float2half_rn(ox * inv);
        oh.y = __float2half_rn(oy * inv);
        *(__half2*)(ao + ob + 2 * lane) = oh;
        __syncwarp();
    }
}

// ---------------- orchestration ----------------
extern "C" void kernel_launch(void* const* d_in, const int* in_sizes, int n_in,
                              void* d_out, int out_size) {
    const int*   tokens  = (const int*)  d_in[0];
    const int*   attmask = (const int*)  d_in[1];
    const float* tok_emb = (const float*)d_in[2];
    const float* pos_emb = (const float*)d_in[3];
    const float* Wq      = (const float*)d_in[4];
    const float* Wk      = (const float*)d_in[5];
    const float* Wv      = (const float*)d_in[6];
    const float* Wo      = (const float*)d_in[7];
    const float* bo      = (const float*)d_in[8];
    const float* ln1_g   = (const float*)d_in[9];
    const float* ln1_b   = (const float*)d_in[10];
    const float* ln2_g   = (const float*)d_in[11];
    const float* ln2_b   = (const float*)d_in[12];
    const float* W1      = (const float*)d_in[13];
    const float* b1      = (const float*)d_in[14];
    const float* W2      = (const float*)d_in[15];
    const float* b2      = (const float*)d_in[16];

    float* x = (float*)d_out;

    __half *h, *qkv, *ao, *ff, *wt;
    cudaGetSymbolAddress((void**)&h,   g_h);
    cudaGetSymbolAddress((void**)&qkv, g_qkv);
    cudaGetSymbolAddress((void**)&ao,  g_ao);
    cudaGetSymbolAddress((void**)&ff,  g_ff);
    cudaGetSymbolAddress((void**)&wt,  g_wt);

    cudaFuncSetAttribute(mma_gemm<0>, cudaFuncAttributeMaxDynamicSharedMemorySize, GEMM_SMEM);
    cudaFuncSetAttribute(mma_gemm<1>, cudaFuncAttributeMaxDynamicSharedMemorySize, GEMM_SMEM);
    cudaFuncSetAttribute(mma_gemm<2>, cudaFuncAttributeMaxDynamicSharedMemorySize, GEMM_SMEM);

    prep_kernel<<<dim3(1024, 6, Lc), dim3(32, 8)>>>(Wq, Wk, Wv, Wo, W1, W2, wt);
    embed_kernel<<<ROWS, 128>>>(tokens, tok_emb, pos_emb, x);

    for (int l = 0; l < Lc; l++) {
        const __half* w = wt + (size_t)l * WT_LAYER;

        ln_kernel<<<1024, 256>>>(x, ln1_g + l * Ec, ln1_b + l * Ec, h);

        mma_gemm<0><<<dim3(QKVN / GBN, ROWS / GBM), 256, GEMM_SMEM>>>(
            h, w + WT_QKV_OFF, nullptr, nullptr, nullptr, qkv, QKVN, Ec);

        attn_kernel<<<Bc * Hc * (Tc / ATT), 256>>>(qkv, attmask, ao);

        mma_gemm<2><<<dim3(Ec / GBN, ROWS / GBM), 256, GEMM_SMEM>>>(
            ao, w + WT_WO_OFF, bo + l * Ec, x, x, nullptr, Ec, Ec);

        ln_kernel<<<1024, 256>>>(x, ln2_g + l * Ec, ln2_b + l * Ec, h);

        mma_gemm<1><<<dim3(FFc / GBN, ROWS / GBM), 256, GEMM_SMEM>>>(
            h, w + WT_W1_OFF, b1 + l * FFc, nullptr, nullptr, ff, FFc, Ec);

        mma_gemm<2><<<dim3(Ec / GBN, ROWS / GBM), 256, GEMM_SMEM>>>(
            ff, w + WT_W2_OFF, b2 + l * Ec, x, x, nullptr, Ec, FFc);
    }
    (void)in_sizes; (void)n_in; (void)out_size;
}

// round 11
// speedup vs baseline: 2.6749x; 1.0079x over previous
#include <cuda_runtime.h>
#include <cuda_fp16.h>
#include <cstdint>

// ---------------- problem constants ----------------
#define Bc   2
#define Tc   4096
#define Ec   512
#define Hc   8
#define Dc   64
#define FFc  2048
#define Lc   2
#define WINc 16
#define NW   33
#define ROWS (Bc*Tc)      // 8192
#define EPSc 1e-5f
#define QKVN (3*Ec)       // 1536

#define WT_QKV_OFF 0
#define WT_WO_OFF  (3*Ec*Ec)
#define WT_W1_OFF  (4*Ec*Ec)
#define WT_W2_OFF  (WT_W1_OFF + FFc*Ec)
#define WT_LAYER   (WT_W2_OFF + Ec*FFc)

// ---------------- scratch ----------------
__device__ __half g_h   [(size_t)ROWS*Ec];
__device__ __half g_qkv [(size_t)ROWS*QKVN];
__device__ __half g_ao  [(size_t)ROWS*Ec];
__device__ __half g_ff  [(size_t)ROWS*FFc];
__device__ __half g_wt  [(size_t)Lc*WT_LAYER];

// ---------------- helpers ----------------
__device__ __forceinline__ uint32_t smem_u32(const void* p) {
    uint32_t a;
    asm("{ .reg .u64 t; cvta.to.shared.u64 t, %1; cvt.u32.u64 %0, t; }" : "=r"(a) : "l"(p));
    return a;
}
#define SW128(x) ((x) ^ (((x) >> 3) & 0x70))

#define CP16(dst, src) \
    asm volatile("cp.async.cg.shared.global [%0], [%1], 16;" :: "r"(dst), "l"(src) : "memory")
#define CPCOMMIT() asm volatile("cp.async.commit_group;" ::: "memory")

__device__ __forceinline__ void ldmx4(uint32_t& r0, uint32_t& r1, uint32_t& r2, uint32_t& r3,
                                      uint32_t addr) {
    asm volatile("ldmatrix.sync.aligned.m8n8.x4.shared.b16 {%0,%1,%2,%3}, [%4];"
                 : "=r"(r0), "=r"(r1), "=r"(r2), "=r"(r3) : "r"(addr));
}
__device__ __forceinline__ void mma16816(float* c, const uint32_t* a, const uint32_t* b) {
    asm volatile("mma.sync.aligned.m16n8k16.row.col.f32.f16.f16.f32 "
                 "{%0,%1,%2,%3}, {%4,%5,%6,%7}, {%8,%9}, {%0,%1,%2,%3};"
                 : "+f"(c[0]), "+f"(c[1]), "+f"(c[2]), "+f"(c[3])
                 : "r"(a[0]), "r"(a[1]), "r"(a[2]), "r"(a[3]), "r"(b[0]), "r"(b[1]));
}

// ---------------- embedding ----------------
__global__ void embed_kernel(const int* __restrict__ tokens,
                             const float* __restrict__ tok_emb,
                             const float* __restrict__ pos_emb,
                             float* __restrict__ x) {
    int row = blockIdx.x;
    int t   = row & (Tc - 1);
    int tok = tokens[row];
    int e   = threadIdx.x * 4;
    float4 a = *(const float4*)(tok_emb + (size_t)tok * Ec + e);
    float4 p = *(const float4*)(pos_emb + (size_t)t   * Ec + e);
    a.x += p.x; a.y += p.y; a.z += p.z; a.w += p.w;
    *(float4*)(x + (size_t)row * Ec + e) = a;
}

// ---------------- layernorm -> fp16 ----------------
__global__ void ln_kernel(const float* __restrict__ x,
                          const float* __restrict__ g,
                          const float* __restrict__ b,
                          __half* __restrict__ y) {
    int warp = (blockIdx.x * blockDim.x + threadIdx.x) >> 5;
    int lane = threadIdx.x & 31;
    if (warp >= ROWS) return;
    const float* xr = x + (size_t)warp * Ec;
    float v[16];
    float s = 0.f;
#pragma unroll
    for (int i = 0; i < 16; i++) { v[i] = xr[lane + i * 32]; s += v[i]; }
#pragma unroll
    for (int o = 16; o > 0; o >>= 1) s += __shfl_xor_sync(0xffffffffu, s, o);
    float mean = s * (1.f / Ec);
    float ss = 0.f;
#pragma unroll
    for (int i = 0; i < 16; i++) { float d = v[i] - mean; ss += d * d; }
#pragma unroll
    for (int o = 16; o > 0; o >>= 1) ss += __shfl_xor_sync(0xffffffffu, ss, o);
    float inv = rsqrtf(ss * (1.f / Ec) + EPSc);
    size_t rb = (size_t)warp * Ec;
#pragma unroll
    for (int i = 0; i < 16; i++) {
        int idx = lane + i * 32;
        y[rb + idx] = __float2half_rn((v[i] - mean) * inv * g[idx] + b[idx]);
    }
}

// ---------------- fused weight prep (fp16 transpose) ----------------
__global__ void prep_kernel(const float* __restrict__ Wq, const float* __restrict__ Wk,
                            const float* __restrict__ Wv, const float* __restrict__ Wo,
                            const float* __restrict__ W1, const float* __restrict__ W2,
                            __half* __restrict__ thi) {
    int l = blockIdx.z, y = blockIdx.y;
    int K = (y == 5) ? FFc : Ec;
    int N = (y == 4) ? FFc : Ec;
    int ntiles = N >> 5;
    int nt = blockIdx.x % ntiles;
    int kt = blockIdx.x / ntiles;
    if (kt >= (K >> 5)) return;

    const float* W; size_t doff;
    switch (y) {
        case 0: W = Wq + (size_t)l * Ec * Ec;  doff = WT_QKV_OFF;            break;
        case 1: W = Wk + (size_t)l * Ec * Ec;  doff = WT_QKV_OFF + Ec * Ec;  break;
        case 2: W = Wv + (size_t)l * Ec * Ec;  doff = WT_QKV_OFF + 2*Ec*Ec;  break;
        case 3: W = Wo + (size_t)l * Ec * Ec;  doff = WT_WO_OFF;             break;
        case 4: W = W1 + (size_t)l * Ec * FFc; doff = WT_W1_OFF;             break;
        default:W = W2 + (size_t)l * FFc * Ec; doff = WT_W2_OFF;             break;
    }
    doff += (size_t)l * WT_LAYER;

    __shared__ float tile[32][33];
    int n0 = nt * 32, k0 = kt * 32;
    int tx = threadIdx.x, ty = threadIdx.y;
#pragma unroll
    for (int i = 0; i < 32; i += 8)
        tile[ty + i][tx] = W[(size_t)(k0 + ty + i) * N + n0 + tx];
    __syncthreads();
#pragma unroll
    for (int i = 0; i < 32; i += 8) {
        float v = tile[tx][ty + i];
        thi[doff + (size_t)(n0 + ty + i) * K + k0 + tx] = __float2half_rn(v);
    }
}

// ---------------- mma.sync GEMM: CTA 128x128, warp 64x32, 2 CTAs/SM ----------
// Single fp16 pass, 3-stage cp.async pipeline.
// EPI: 0 = fp16 out; 1 = bias+relu -> fp16; 2 = bias+residual fp32
#define GBM 128
#define GBN 128
#define GBK 64
#define A_OFF   0
#define B_OFF   16384
#define GSTG    32768
#define NSTAGE  3
#define GEMM_SMEM (NSTAGE*GSTG)   // 98304; 2 CTAs/SM = 192KB

__device__ __forceinline__ void load_chunk(
    uint32_t base, int tid, int rowA0, int rowB0, int k0, int K,
    const __half* __restrict__ A, const __half* __restrict__ B) {
#pragma unroll
    for (int i = tid; i < 1024; i += 256) {            // A: 128 rows x 8 vec16
        int r = i >> 3, j = i & 7;
        uint32_t sw = SW128((uint32_t)((r << 7) + (j << 4)));
        CP16(base + A_OFF + sw, A + (size_t)(rowA0 + r) * K + k0 + j * 8);
    }
#pragma unroll
    for (int i = tid; i < 1024; i += 256) {            // B: 128 rows x 8 vec16
        int r = i >> 3, j = i & 7;
        uint32_t sw = SW128((uint32_t)((r << 7) + (j << 4)));
        CP16(base + B_OFF + sw, B + (size_t)(rowB0 + r) * K + k0 + j * 8);
    }
}

template <int EPI>
__global__ __launch_bounds__(256, 2)
void mma_gemm(const __half* __restrict__ A, const __half* __restrict__ B,
              const float* __restrict__ bias, const float* __restrict__ res,
              float* __restrict__ outF, __half* __restrict__ outH,
              int N, int K) {
    extern __shared__ char smem[];
    uint32_t sb = smem_u32(smem);
    int tid = threadIdx.x, wid = tid >> 5, lane = tid & 31;

    int rowA0 = blockIdx.y * GBM;
    int rowB0 = blockIdx.x * GBN;
    int warpM0 = (wid >> 2) * 64;     // 2 warp rows
    int warpN0 = (wid & 3) * 32;      // 4 warp cols
    const int KC = K / GBK;

    float acc[4][4][4];               // 64 regs
#pragma unroll
    for (int i = 0; i < 4; i++)
#pragma unroll
        for (int j = 0; j < 4; j++)
#pragma unroll
            for (int r = 0; r < 4; r++) acc[i][j][r] = 0.f;

    load_chunk(sb,        tid, rowA0, rowB0, 0,   K, A, B); CPCOMMIT();
    load_chunk(sb + GSTG, tid, rowA0, rowB0, GBK, K, A, B); CPCOMMIT();

    int mat  = lane >> 3;
    int mrow = lane & 7;
    int rsel = (mat & 1) * 8 + mrow;
    int csel = mat >> 1;

    for (int c = 0; c < KC; c++) {
        uint32_t base = sb + (uint32_t)(c % NSTAGE) * GSTG;
        if (c < KC - 1) asm volatile("cp.async.wait_group 1;" ::: "memory");
        else            asm volatile("cp.async.wait_group 0;" ::: "memory");
        __syncthreads();
        if (c + 2 < KC) {   // prefetch into stage (c+2)%3 (freed at end of iter c-1)
            load_chunk(sb + (uint32_t)((c + 2) % NSTAGE) * GSTG,
                       tid, rowA0, rowB0, (c + 2) * GBK, K, A, B);
            CPCOMMIT();
        }

#pragma unroll
        for (int kk = 0; kk < 4; kk++) {
            int chunk = 2 * kk + csel;
            uint32_t ah[4][4];
#pragma unroll
            for (int mi = 0; mi < 4; mi++) {
                uint32_t sw = SW128((uint32_t)((warpM0 + mi * 16 + rsel) << 7) + (chunk << 4));
                ldmx4(ah[mi][0], ah[mi][1], ah[mi][2], ah[mi][3], base + A_OFF + sw);
            }
            uint32_t bf[4][2];
#pragma unroll
            for (int bj = 0; bj < 2; bj++) {
                uint32_t sw = SW128((uint32_t)((warpN0 + bj * 16 + rsel) << 7) + (chunk << 4));
                uint32_t r0, r1, r2, r3;
                ldmx4(r0, r1, r2, r3, base + B_OFF + sw);
                bf[2*bj][0] = r0; bf[2*bj][1] = r2; bf[2*bj+1][0] = r1; bf[2*bj+1][1] = r3;
            }
#pragma unroll
            for (int mi = 0; mi < 4; mi++)
#pragma unroll
                for (int nf = 0; nf < 4; nf++)
                    mma16816(acc[mi][nf], ah[mi], bf[nf]);
        }
        __syncthreads();   // all warps done with stage c before it is refilled
    }

    // ---------------- epilogue ----------------
    int grp = lane >> 2;
    int qd  = lane & 3;
#pragma unroll
    for (int mi = 0; mi < 4; mi++) {
#pragma unroll
        for (int half = 0; half < 2; half++) {
            int m = rowA0 + warpM0 + mi * 16 + half * 8 + grp;
            size_t orow = (size_t)m * N;
#pragma unroll
            for (int nf = 0; nf < 4; nf++) {
                int n = rowB0 + warpN0 + nf * 8 + qd * 2;
                float v0 = acc[mi][nf][half * 2 + 0];
                float v1 = acc[mi][nf][half * 2 + 1];
                if (EPI == 0) {
                    __half2 hh;
                    hh.x = __float2half_rn(v0);
                    hh.y = __float2half_rn(v1);
                    *(__half2*)(outH + orow + n) = hh;
                } else if (EPI == 2) {
                    float2 rr = *(const float2*)(res + orow + n);
                    float2 vv;
                    vv.x = v0 + bias[n]     + rr.x;
                    vv.y = v1 + bias[n + 1] + rr.y;
                    *(float2*)(outF + orow + n) = vv;
                } else {
                    v0 = fmaxf(v0 + bias[n],     0.f);
                    v1 = fmaxf(v1 + bias[n + 1], 0.f);
                    __half2 hh;
                    hh.x = __float2half_rn(v0);
                    hh.y = __float2half_rn(v1);
                    *(__half2*)(outH + orow + n) = hh;
                }
            }
        }
    }
}

// ---------------- sliding-window attention: lane-per-window ------------------
#define ATT 64
#define AROWS (ATT + 2*WINc)   // 96
#define KPITCH 66

__global__ void attn_kernel(const __half* __restrict__ qkv,
                            const int* __restrict__ mask,
                            __half* __restrict__ ao) {
    __shared__ __half sK[AROWS * KPITCH];
    __shared__ __half sV[AROWS * KPITCH];
    __shared__ float  sp[8][40];
    __shared__ int    sM[AROWS];

    int bid  = blockIdx.x;
    int tile = bid & (Tc / ATT - 1);
    int h    = (bid >> 6) & (Hc - 1);
    int b    = bid >> 9;
    int t0   = tile * ATT;
    int tid  = threadIdx.x;

    if (tid < AROWS) {
        int tc = t0 - WINc + tid;
        sM[tid] = (tc >= 0 && tc < Tc) ? mask[b * Tc + tc] : 0;
    }
    for (int i = tid; i < AROWS * 32; i += 256) {
        int r = i >> 5, j = i & 31;
        int tc = t0 - WINc + r;
        uint32_t kv = 0, vv = 0;
        if (tc >= 0 && tc < Tc) {
            const __half* kr = qkv + (size_t)(b * Tc + tc) * QKVN + Ec + h * Dc;
            const __half* vr = qkv + (size_t)(b * Tc + tc) * QKVN + 2 * Ec + h * Dc;
            kv = *(const uint32_t*)(kr + j * 2);
            vv = *(const uint32_t*)(vr + j * 2);
        }
        *(uint32_t*)(sK + r * KPITCH + j * 2) = kv;
        *(uint32_t*)(sV + r * KPITCH + j * 2) = vv;
    }
    __syncthreads();

    int wid = tid >> 5, lane = tid & 31;
    for (int tt = wid; tt < ATT; tt += 8) {
        int t = t0 + tt;
        const __half2* q2 = (const __half2*)(qkv + (size_t)(b * Tc + t) * QKVN + h * Dc);

        int w = lane;
        bool valid = sM[tt + w] > 0;
        float s = -1e9f;
        if (valid) {
            const __half2* kr = (const __half2*)(sK + (tt + w) * KPITCH);
            float p = 0.f;
#pragma unroll
            for (int j = 0; j < 32; j++) {
                float2 qf = __half22float2(q2[j]);
                float2 kf = __half22float2(kr[j]);
                p += qf.x * kf.x + qf.y * kf.y;
            }
            s = p * 0.125f;
        }
        float s32 = -1e9f;
        {
            bool v2 = sM[tt + 32] > 0;
            float2 qf = __half22float2(q2[lane]);
            float2 kf = __half22float2(*(const __half2*)(sK + (tt + 32) * KPITCH + 2 * lane));
            float pp = qf.x * kf.x + qf.y * kf.y;
#pragma unroll
            for (int o = 16; o > 0; o >>= 1) pp += __shfl_xor_sync(0xffffffffu, pp, o);
            if (v2) s32 = pp * 0.125f;
        }
        float m = s;
#pragma unroll
        for (int o = 16; o > 0; o >>= 1) m = fmaxf(m, __shfl_xor_sync(0xffffffffu, m, o));
        m = fmaxf(m, s32);
        float e  = __expf(s - m);
        float es = e;
#pragma unroll
        for (int o = 16; o > 0; o >>= 1) es += __shfl_xor_sync(0xffffffffu, es, o);
        float e32 = __expf(s32 - m);
        float inv = 1.f / (es + e32);
        sp[wid][lane] = e;
        if (lane == 0) sp[wid][32] = e32;
        __syncwarp();

        float ox = 0.f, oy = 0.f;
#pragma unroll
        for (int ww = 0; ww < NW; ww++) {
            float a = sp[wid][ww];
            float2 vf = __half22float2(*(const __half2*)(sV + (tt + ww) * KPITCH + 2 * lane));
            ox += a * vf.x;
            oy += a * vf.y;
        }
        size_t ob = (size_t)(b * Tc + t) * Ec + h * Dc;
        __half2 oh;
        oh.x = __float2half_rn(ox * inv);
        oh.y = __float2half_rn(oy * inv);
        *(__half2*)(ao + ob + 2 * lane) = oh;
        __syncwarp();
    }
}

// ---------------- orchestration ----------------
extern "C" void kernel_launch(void* const* d_in, const int* in_sizes, int n_in,
                              void* d_out, int out_size) {
    const int*   tokens  = (const int*)  d_in[0];
    const int*   attmask = (const int*)  d_in[1];
    const float* tok_emb = (const float*)d_in[2];
    const float* pos_emb = (const float*)d_in[3];
    const float* Wq      = (const float*)d_in[4];
    const float* Wk      = (const float*)d_in[5];
    const float* Wv      = (const float*)d_in[6];
    const float* Wo      = (const float*)d_in[7];
    const float* bo      = (const float*)d_in[8];
    const float* ln1_g   = (const float*)d_in[9];
    const float* ln1_b   = (const float*)d_in[10];
    const float* ln2_g   = (const float*)d_in[11];
    const float* ln2_b   = (const float*)d_in[12];
    const float* W1      = (const float*)d_in[13];
    const float* b1      = (const float*)d_in[14];
    const float* W2      = (const float*)d_in[15];
    const float* b2      = (const float*)d_in[16];

    float* x = (float*)d_out;

    __half *h, *qkv, *ao, *ff, *wt;
    cudaGetSymbolAddress((void**)&h,   g_h);
    cudaGetSymbolAddress((void**)&qkv, g_qkv);
    cudaGetSymbolAddress((void**)&ao,  g_ao);
    cudaGetSymbolAddress((void**)&ff,  g_ff);
    cudaGetSymbolAddress((void**)&wt,  g_wt);

    cudaFuncSetAttribute(mma_gemm<0>, cudaFuncAttributeMaxDynamicSharedMemorySize, GEMM_SMEM);
    cudaFuncSetAttribute(mma_gemm<1>, cudaFuncAttributeMaxDynamicSharedMemorySize, GEMM_SMEM);
    cudaFuncSetAttribute(mma_gemm<2>, cudaFuncAttributeMaxDynamicSharedMemorySize, GEMM_SMEM);

    prep_kernel<<<dim3(1024, 6, Lc), dim3(32, 8)>>>(Wq, Wk, Wv, Wo, W1, W2, wt);
    embed_kernel<<<ROWS, 128>>>(tokens, tok_emb, pos_emb, x);

    for (int l = 0; l < Lc; l++) {
        const __half* w = wt + (size_t)l * WT_LAYER;

        ln_kernel<<<1024, 256>>>(x, ln1_g + l * Ec, ln1_b + l * Ec, h);

        mma_gemm<0><<<dim3(QKVN / GBN, ROWS / GBM), 256, GEMM_SMEM>>>(
            h, w + WT_QKV_OFF, nullptr, nullptr, nullptr, qkv, QKVN, Ec);

        attn_kernel<<<Bc * Hc * (Tc / ATT), 256>>>(qkv, attmask, ao);

        mma_gemm<2><<<dim3(Ec / GBN, ROWS / GBM), 256, GEMM_SMEM>>>(
            ao, w + WT_WO_OFF, bo + l * Ec, x, x, nullptr, Ec, Ec);

        ln_kernel<<<1024, 256>>>(x, ln2_g + l * Ec, ln2_b + l * Ec, h);

        mma_gemm<1><<<dim3(FFc / GBN, ROWS / GBM), 256, GEMM_SMEM>>>(
            h, w + WT_W1_OFF, b1 + l * FFc, nullptr, nullptr, ff, FFc, Ec);

        mma_gemm<2><<<dim3(Ec / GBN, ROWS / GBM), 256, GEMM_SMEM>>>(
            ff, w + WT_W2_OFF, b2 + l * Ec, x, x, nullptr, Ec, FFc);
    }
    (void)in_sizes; (void)n_in; (void)out_size;
}